// round 11
// baseline (speedup 1.0000x reference)
#include <cuda_runtime.h>
#include <cuda_bf16.h>

// ---------------- problem constants ----------------
#define W_IMG 135
#define H_IMG 240
#define NPIX (W_IMG * H_IMG)
#define NF 1000
#define NV 600
#define TSZ 16           // tile is 16x16 pixels
#define TX 9             // ceil(135/16)
#define TY 15            // 240/16
#define NT (TX * TY)     // 135 tiles
#define NSLICE 8         // face-parallel slices per tile
#define NCAND ((NF + NSLICE - 1) / NSLICE)   // 125 candidates per slice
#define NTHR 128         // threads per render block (2 pixels each)
#define BLUR_F 9.21024036697585e-04f
#define INV_SIGMA 10000.0f
#define RB 0.0315f       // > sqrt(BLUR) = 0.0303

// ---------------- device scratch (no allocations; zero-initialized) ----------------
__device__ float4 g_face[NF * 3];   // {ax,ay,e0x,e0y} {e1x,e1y,e2x,e2y} {r0,r1,r2,-}
__device__ float4 g_bbox[NF];       // {minx, maxx, miny, maxy} pre-expanded by RB
__device__ int    g_tileTicket[NT]; // 0 at entry (self-resetting)
__device__ float  g_Spart[NSLICE * NT * (2 * NTHR)];
__device__ float  g_lossAcc;        // 0 at entry (self-resetting)
__device__ int    g_ticket;         // 0 at entry (self-resetting)

// ---------------- prep: projection + face setup + bbox (NO atomics) ----------------
__global__ void __launch_bounds__(256)
sil_prep_kernel(const float* __restrict__ verts, const int* __restrict__ faces) {
    int f = blockIdx.x * 256 + threadIdx.x;
    if (f >= NF) return;
    int i0 = faces[3 * f + 0];
    int i1 = faces[3 * f + 1];
    int i2 = faces[3 * f + 2];

    float x0 = verts[3 * i0], y0 = verts[3 * i0 + 1], z0 = verts[3 * i0 + 2];
    float x1 = verts[3 * i1], y1 = verts[3 * i1 + 1], z1 = verts[3 * i1 + 2];
    float x2 = verts[3 * i2], y2 = verts[3 * i2 + 1], z2 = verts[3 * i2 + 2];

    float tz = (z0 + z1 + z2) * (1.0f / 3.0f);
    if (!(tz > 1e-6f)) {   // valid=false everywhere -> empty bbox, never selected
        g_bbox[f] = make_float4(1e9f, -1e9f, 1e9f, -1e9f);
        return;
    }

    const float SX = (1.0f / 1024.0f) * (float)W_IMG;
    const float SY = (1.0f / 1024.0f) * (float)H_IMG;
    float inv0 = 1.0f / fmaxf(z0, 1e-6f);
    float inv1 = 1.0f / fmaxf(z1, 1e-6f);
    float inv2 = 1.0f / fmaxf(z2, 1e-6f);
    float ax = (1000.0f * (-x0) * inv0 + 512.0f) * SX;
    float ay = (1000.0f * (-y0) * inv0 + 512.0f) * SY;
    float bx = (1000.0f * (-x1) * inv1 + 512.0f) * SX;
    float by = (1000.0f * (-y1) * inv1 + 512.0f) * SY;
    float cx = (1000.0f * (-x2) * inv2 + 512.0f) * SX;
    float cy = (1000.0f * (-y2) * inv2 + 512.0f) * SY;

    float e0x = bx - ax, e0y = by - ay;
    float e1x = cx - bx, e1y = cy - by;
    float e2x = ax - cx, e2y = ay - cy;
    float r0 = 1.0f / (e0x * e0x + e0y * e0y + 1e-12f);
    float r1 = 1.0f / (e1x * e1x + e1y * e1y + 1e-12f);
    float r2 = 1.0f / (e2x * e2x + e2y * e2y + 1e-12f);
    g_face[3 * f + 0] = make_float4(ax, ay, e0x, e0y);
    g_face[3 * f + 1] = make_float4(e1x, e1y, e2x, e2y);
    g_face[3 * f + 2] = make_float4(r0, r1, r2, 0.0f);

    // exact culling bbox: contribution is zero > sqrt(BLUR) away from triangle
    g_bbox[f] = make_float4(
        fminf(ax, fminf(bx, cx)) - RB,
        fmaxf(ax, fmaxf(bx, cx)) + RB,
        fminf(ay, fminf(by, cy)) - RB,
        fmaxf(ay, fmaxf(by, cy)) + RB);
}

// per-pixel-pair face evaluation: returns softplus contributions via S0/S1
__device__ __forceinline__ void eval_face(
    const float4& A, const float4& B, const float4& R,
    float px, float py0, float py1, float& S0, float& S1)
{
    // x-direction terms shared between the two pixels (same px)
    float apx = px - A.x;
    float bpx = apx - A.z;
    float cpx = bpx - B.x;

    #pragma unroll
    for (int h = 0; h < 2; h++) {
        float py = h ? py1 : py0;
        float apy = py - A.y;
        float bpy = apy - A.w;
        float cpy = bpy - B.y;

        float c0 = A.z * apy - A.w * apx;
        float c1 = B.x * bpy - B.y * bpx;
        float c2 = B.z * cpy - B.w * cpx;
        bool pos = (c0 >= 0.0f) & (c1 >= 0.0f) & (c2 >= 0.0f);
        bool neg = (c0 <= 0.0f) & (c1 <= 0.0f) & (c2 <= 0.0f);

        float t0 = fminf(fmaxf((apx * A.z + apy * A.w) * R.x, 0.0f), 1.0f);
        float t1 = fminf(fmaxf((bpx * B.x + bpy * B.y) * R.y, 0.0f), 1.0f);
        float t2 = fminf(fmaxf((cpx * B.z + cpy * B.w) * R.z, 0.0f), 1.0f);
        float dx0 = apx - t0 * A.z, dy0 = apy - t0 * A.w;
        float dx1 = bpx - t1 * B.x, dy1 = bpy - t1 * B.y;
        float dx2 = cpx - t2 * B.z, dy2 = cpy - t2 * B.w;
        float d0 = dx0 * dx0 + dy0 * dy0;
        float d1 = dx1 * dx1 + dy1 * dy1;
        float d2 = dx2 * dx2 + dy2 * dy2;
        float dmin = fminf(d0, fminf(d1, d2));

        bool inside = pos | neg;
        if (inside | (dmin <= BLUR_F)) {
            float x = inside ? dmin * INV_SIGMA : -dmin * INV_SIGMA;
            // log1p(-sigmoid(x)) = -softplus(x)
            float sp = fmaxf(x, 0.0f) + __logf(1.0f + __expf(-fabsf(x)));
            if (h) S1 -= sp; else S0 -= sp;
        }
    }
}

// ---------------- render: per-block culling + eval(2px/thread) + fused finalize ----------------
__global__ void __launch_bounds__(NTHR)
sil_render_kernel(const float* __restrict__ gt, float* __restrict__ out, int sil_off) {
    __shared__ float4 sF[NTHR * 3];
    __shared__ int    sCnt[4];
    __shared__ float  sRed[4];
    __shared__ int    sLast;

    int b   = blockIdx.x;
    int t   = b % NT;          // interleave: same-tile slices land on different SMs
    int s   = b / NT;          // slice id
    int tid = threadIdx.x;
    int lane = tid & 31, warp = tid >> 5;
    int tx  = t % TX, ty = t / TX;
    int lx  = tid % TSZ, ly = tid / TSZ;          // ly in [0,8)
    int ix  = tx * TSZ + lx;
    int iy0 = ty * TSZ + ly;
    int iy1 = iy0 + 8;
    float px  = (float)ix + 0.5f;
    float py0 = (float)iy0 + 0.5f;
    float py1 = (float)iy1 + 0.5f;

    // tile pixel-center rect
    float rx0 = (float)(tx * TSZ) + 0.5f;
    float rx1 = (float)(tx * TSZ + TSZ - 1) + 0.5f;
    float ry0 = (float)(ty * TSZ) + 0.5f;
    float ry1 = (float)(ty * TSZ + TSZ - 1) + 0.5f;

    // ---- cull: thread tid tests candidate face f = s + tid*NSLICE ----
    // per-warp segment compaction (tid-ascending => face order preserved)
    bool keep = false;
    int  fidx = 0;
    if (tid < NCAND) {
        int f = s + tid * NSLICE;
        float4 bb = g_bbox[f];   // minx, maxx, miny, maxy
        keep = (bb.y >= rx0) & (bb.x <= rx1) & (bb.w >= ry0) & (bb.z <= ry1);
        fidx = f;
    }
    unsigned mask = __ballot_sync(0xFFFFFFFFu, keep);
    if (keep) {
        int pos = warp * 32 + __popc(mask & ((1u << lane) - 1u));
        sF[pos * 3 + 0] = g_face[fidx * 3 + 0];
        sF[pos * 3 + 1] = g_face[fidx * 3 + 1];
        sF[pos * 3 + 2] = g_face[fidx * 3 + 2];
    }
    if (lane == 0) sCnt[warp] = __popc(mask);
    __syncthreads();

    // ---- eval over compacted per-warp segments ----
    float S0 = 0.0f, S1 = 0.0f;
    #pragma unroll
    for (int w = 0; w < 4; w++) {
        int mw = sCnt[w];
        #pragma unroll 2
        for (int j = 0; j < mw; j++) {
            int idx = w * 32 + j;
            eval_face(sF[idx * 3 + 0], sF[idx * 3 + 1], sF[idx * 3 + 2],
                      px, py0, py1, S0, S1);
        }
    }

    g_Spart[b * (2 * NTHR) + tid]        = S0;
    g_Spart[b * (2 * NTHR) + NTHR + tid] = S1;

    // ----- per-tile ticket: last-arriving block finalizes this tile -----
    __threadfence();
    __syncthreads();
    if (tid == 0)
        sLast = (atomicAdd(&g_tileTicket[t], 1) == NSLICE - 1) ? 1 : 0;
    __syncthreads();
    if (!sLast) return;

    float Ssum0 = 0.0f, Ssum1 = 0.0f;
    #pragma unroll
    for (int sl = 0; sl < NSLICE; sl++) {
        int base = (sl * NT + t) * (2 * NTHR);
        Ssum0 += g_Spart[base + tid];
        Ssum1 += g_Spart[base + NTHR + tid];
    }

    float alpha0 = 1.0f - __expf(Ssum0);
    float alpha1 = 1.0f - __expf(Ssum1);
    float diff = 0.0f;
    if (ix < W_IMG) {
        out[sil_off + iy0 * W_IMG + ix] = alpha0;
        out[sil_off + iy1 * W_IMG + ix] = alpha1;
        diff = fabsf(alpha0 - gt[iy0 * W_IMG + ix]) +
               fabsf(alpha1 - gt[iy1 * W_IMG + ix]);
    }
    #pragma unroll
    for (int o = 16; o > 0; o >>= 1)
        diff += __shfl_down_sync(0xFFFFFFFFu, diff, o);
    if (lane == 0) sRed[warp] = diff;
    __syncthreads();

    if (tid == 0) {
        g_tileTicket[t] = 0;   // reset for next graph replay
        atomicAdd(&g_lossAcc, sRed[0] + sRed[1] + sRed[2] + sRed[3]);
        __threadfence();
        int done = atomicAdd(&g_ticket, 1);
        if (done == NT - 1) {
            float total = atomicExch(&g_lossAcc, 0.0f);   // read + reset
            if (sil_off) out[0] = total * (1.0f / (float)NPIX);
            g_ticket = 0;
        }
    }
}

// ---------------- launch ----------------
extern "C" void kernel_launch(void* const* d_in, const int* in_sizes, int n_in,
                              void* d_out, int out_size) {
    const float* verts = nullptr;
    const float* gt    = nullptr;
    const int*   faces = nullptr;
    for (int i = 0; i < n_in; i++) {
        if (in_sizes[i] == NV * 3)  verts = (const float*)d_in[i];
        else if (in_sizes[i] == NPIX) gt  = (const float*)d_in[i];
        else if (in_sizes[i] == NF * 3) faces = (const int*)d_in[i];
    }
    float* out = (float*)d_out;
    int sil_off = (out_size > NPIX) ? 1 : 0;   // [loss, sil...] vs [sil...]

    sil_prep_kernel<<<(NF + 255) / 256, 256>>>(verts, faces);
    sil_render_kernel<<<NT * NSLICE, NTHR>>>(gt, out, sil_off);
}

// round 13
// speedup vs baseline: 1.3041x; 1.3041x over previous
#include <cuda_runtime.h>
#include <cuda_bf16.h>

// ---------------- problem constants ----------------
#define W_IMG 135
#define H_IMG 240
#define NPIX (W_IMG * H_IMG)
#define NF 1000
#define NV 600
#define TW 16            // tile width (pixels)
#define TH 8             // tile height (pixels)
#define TX 9             // ceil(135/16)
#define TY 30            // 240/8
#define NT (TX * TY)     // 270 tiles
#define NSLICE 16        // face-parallel slices per tile (R7-proven for render)
#define NCAND ((NF + NSLICE - 1) / NSLICE)   // 63 candidates per slice
#define NTHR (TW * TH)   // 128 threads per render block
#define BLUR_F 9.21024036697585e-04f
#define INV_SIGMA 10000.0f
#define RB 0.0315f       // > sqrt(BLUR) = 0.0303

// ---------------- device scratch (no allocations; zero-initialized) ----------------
__device__ float4 g_face[NF * 3];   // {ax,ay,e0x,e0y} {e1x,e1y,e2x,e2y} {r0,r1,r2,-}
__device__ float4 g_bbox[NF];       // {minx, maxx, miny, maxy} pre-expanded by RB
__device__ int    g_tileTicket[NT]; // 0 at entry (self-resetting)
__device__ float  g_Spart[NSLICE * NT * NTHR];
__device__ float  g_lossAcc;        // 0 at entry (self-resetting)
__device__ int    g_ticket;         // 0 at entry (self-resetting)

// ---------------- prep: projection + face setup + bbox (NO atomics) ----------------
__global__ void __launch_bounds__(256)
sil_prep_kernel(const float* __restrict__ verts, const int* __restrict__ faces) {
    int f = blockIdx.x * 256 + threadIdx.x;
    if (f >= NF) return;
    int i0 = faces[3 * f + 0];
    int i1 = faces[3 * f + 1];
    int i2 = faces[3 * f + 2];

    float x0 = verts[3 * i0], y0 = verts[3 * i0 + 1], z0 = verts[3 * i0 + 2];
    float x1 = verts[3 * i1], y1 = verts[3 * i1 + 1], z1 = verts[3 * i1 + 2];
    float x2 = verts[3 * i2], y2 = verts[3 * i2 + 1], z2 = verts[3 * i2 + 2];

    float tz = (z0 + z1 + z2) * (1.0f / 3.0f);
    if (!(tz > 1e-6f)) {   // valid=false everywhere -> empty bbox, never selected
        g_bbox[f] = make_float4(1e9f, -1e9f, 1e9f, -1e9f);
        return;
    }

    const float SX = (1.0f / 1024.0f) * (float)W_IMG;
    const float SY = (1.0f / 1024.0f) * (float)H_IMG;
    float inv0 = 1.0f / fmaxf(z0, 1e-6f);
    float inv1 = 1.0f / fmaxf(z1, 1e-6f);
    float inv2 = 1.0f / fmaxf(z2, 1e-6f);
    float ax = (1000.0f * (-x0) * inv0 + 512.0f) * SX;
    float ay = (1000.0f * (-y0) * inv0 + 512.0f) * SY;
    float bx = (1000.0f * (-x1) * inv1 + 512.0f) * SX;
    float by = (1000.0f * (-y1) * inv1 + 512.0f) * SY;
    float cx = (1000.0f * (-x2) * inv2 + 512.0f) * SX;
    float cy = (1000.0f * (-y2) * inv2 + 512.0f) * SY;

    float e0x = bx - ax, e0y = by - ay;
    float e1x = cx - bx, e1y = cy - by;
    float e2x = ax - cx, e2y = ay - cy;
    float r0 = 1.0f / (e0x * e0x + e0y * e0y + 1e-12f);
    float r1 = 1.0f / (e1x * e1x + e1y * e1y + 1e-12f);
    float r2 = 1.0f / (e2x * e2x + e2y * e2y + 1e-12f);
    g_face[3 * f + 0] = make_float4(ax, ay, e0x, e0y);
    g_face[3 * f + 1] = make_float4(e1x, e1y, e2x, e2y);
    g_face[3 * f + 2] = make_float4(r0, r1, r2, 0.0f);

    // exact culling bbox: contribution is zero > sqrt(BLUR) away from triangle
    g_bbox[f] = make_float4(
        fminf(ax, fminf(bx, cx)) - RB,
        fmaxf(ax, fmaxf(bx, cx)) + RB,
        fminf(ay, fminf(by, cy)) - RB,
        fmaxf(ay, fmaxf(by, cy)) + RB);
}

// ---------------- render: per-block culling + eval + fused finalize ----------------
__global__ void __launch_bounds__(NTHR)
sil_render_kernel(const float* __restrict__ gt, float* __restrict__ out, int sil_off) {
    __shared__ float4 sF[64 * 3];      // capacity: 2 warps x 32 candidates
    __shared__ int    sCnt[2];
    __shared__ float  sRed[4];
    __shared__ int    sLast;

    int b   = blockIdx.x;
    int t   = b % NT;          // interleave: same-tile slices land on different SMs
    int s   = b / NT;          // slice id
    int tid = threadIdx.x;
    int lane = tid & 31, warp = tid >> 5;
    int tx  = t % TX, ty = t / TX;
    int ix  = tx * TW + (tid % TW);
    int iy  = ty * TH + (tid / TW);
    float px = (float)ix + 0.5f;
    float py = (float)iy + 0.5f;

    // tile pixel-center rect
    float rx0 = (float)(tx * TW) + 0.5f;
    float rx1 = (float)(tx * TW + TW - 1) + 0.5f;
    float ry0 = (float)(ty * TH) + 0.5f;
    float ry1 = (float)(ty * TH + TH - 1) + 0.5f;

    // ---- cull: thread tid (< NCAND) tests candidate face f = s + tid*NSLICE ----
    // per-warp segment compaction, tid-ascending => global face order preserved
    bool keep = false;
    int  fidx = 0;
    if (tid < NCAND) {
        int f = s + tid * NSLICE;
        if (f < NF) {
            float4 bb = g_bbox[f];   // minx, maxx, miny, maxy
            keep = (bb.y >= rx0) & (bb.x <= rx1) & (bb.w >= ry0) & (bb.z <= ry1);
            fidx = f;
        }
    }
    unsigned mask = __ballot_sync(0xFFFFFFFFu, keep);
    if (keep) {
        int pos = warp * 32 + __popc(mask & ((1u << lane) - 1u));
        sF[pos * 3 + 0] = g_face[fidx * 3 + 0];
        sF[pos * 3 + 1] = g_face[fidx * 3 + 1];
        sF[pos * 3 + 2] = g_face[fidx * 3 + 2];
    }
    if (warp < 2 && lane == 0) sCnt[warp] = __popc(mask);
    __syncthreads();

    // ---- eval over compacted per-warp segments (order = ascending face id) ----
    float S = 0.0f;
    #pragma unroll
    for (int w = 0; w < 2; w++) {
        int mw = sCnt[w];
        #pragma unroll 2
        for (int j = 0; j < mw; j++) {
            int idx = w * 32 + j;
            float4 A = sF[idx * 3 + 0];   // ax, ay, e0x, e0y
            float4 B = sF[idx * 3 + 1];   // e1x, e1y, e2x, e2y
            float4 R = sF[idx * 3 + 2];   // r0, r1, r2

            float apx = px - A.x, apy = py - A.y;
            float bpx = apx - A.z, bpy = apy - A.w;
            float cpx = bpx - B.x, cpy = bpy - B.y;

            float c0 = A.z * apy - A.w * apx;
            float c1 = B.x * bpy - B.y * bpx;
            float c2 = B.z * cpy - B.w * cpx;
            bool pos = (c0 >= 0.0f) & (c1 >= 0.0f) & (c2 >= 0.0f);
            bool neg = (c0 <= 0.0f) & (c1 <= 0.0f) & (c2 <= 0.0f);

            float t0 = fminf(fmaxf((apx * A.z + apy * A.w) * R.x, 0.0f), 1.0f);
            float t1 = fminf(fmaxf((bpx * B.x + bpy * B.y) * R.y, 0.0f), 1.0f);
            float t2 = fminf(fmaxf((cpx * B.z + cpy * B.w) * R.z, 0.0f), 1.0f);
            float dx0 = apx - t0 * A.z, dy0 = apy - t0 * A.w;
            float dx1 = bpx - t1 * B.x, dy1 = bpy - t1 * B.y;
            float dx2 = cpx - t2 * B.z, dy2 = cpy - t2 * B.w;
            float d0 = dx0 * dx0 + dy0 * dy0;
            float d1 = dx1 * dx1 + dy1 * dy1;
            float d2 = dx2 * dx2 + dy2 * dy2;
            float dmin = fminf(d0, fminf(d1, d2));

            bool inside = pos | neg;
            if (inside | (dmin <= BLUR_F)) {
                float x = inside ? dmin * INV_SIGMA : -dmin * INV_SIGMA;
                // log1p(-sigmoid(x)) = -softplus(x)
                float sp = fmaxf(x, 0.0f) + __logf(1.0f + __expf(-fabsf(x)));
                S -= sp;
            }
        }
    }

    g_Spart[b * NTHR + tid] = S;

    // ----- per-tile ticket: last-arriving block finalizes this tile -----
    __threadfence();
    __syncthreads();
    if (tid == 0)
        sLast = (atomicAdd(&g_tileTicket[t], 1) == NSLICE - 1) ? 1 : 0;
    __syncthreads();
    if (!sLast) return;

    float Ssum = 0.0f;
    #pragma unroll
    for (int sl = 0; sl < NSLICE; sl++)
        Ssum += g_Spart[(sl * NT + t) * NTHR + tid];

    float alpha = 1.0f - __expf(Ssum);
    float diff = 0.0f;
    if (ix < W_IMG) {
        out[sil_off + iy * W_IMG + ix] = alpha;
        diff = fabsf(alpha - gt[iy * W_IMG + ix]);
    }
    #pragma unroll
    for (int o = 16; o > 0; o >>= 1)
        diff += __shfl_down_sync(0xFFFFFFFFu, diff, o);
    if (lane == 0) sRed[warp] = diff;
    __syncthreads();

    if (tid == 0) {
        g_tileTicket[t] = 0;   // reset for next graph replay
        atomicAdd(&g_lossAcc, sRed[0] + sRed[1] + sRed[2] + sRed[3]);
        __threadfence();
        int done = atomicAdd(&g_ticket, 1);
        if (done == NT - 1) {
            float total = atomicExch(&g_lossAcc, 0.0f);   // read + reset
            if (sil_off) out[0] = total * (1.0f / (float)NPIX);
            g_ticket = 0;
        }
    }
}

// ---------------- launch ----------------
extern "C" void kernel_launch(void* const* d_in, const int* in_sizes, int n_in,
                              void* d_out, int out_size) {
    const float* verts = nullptr;
    const float* gt    = nullptr;
    const int*   faces = nullptr;
    for (int i = 0; i < n_in; i++) {
        if (in_sizes[i] == NV * 3)  verts = (const float*)d_in[i];
        else if (in_sizes[i] == NPIX) gt  = (const float*)d_in[i];
        else if (in_sizes[i] == NF * 3) faces = (const int*)d_in[i];
    }
    float* out = (float*)d_out;
    int sil_off = (out_size > NPIX) ? 1 : 0;   // [loss, sil...] vs [sil...]

    sil_prep_kernel<<<(NF + 255) / 256, 256>>>(verts, faces);
    sil_render_kernel<<<NT * NSLICE, NTHR>>>(gt, out, sil_off);
}